// round 2
// baseline (speedup 1.0000x reference)
#include <cuda_runtime.h>
#include <cuda_bf16.h>

#define NBLOCKS 2048
#define NTHREADS 256

__constant__ float c_table[28] = {
    0.05f, 0.02f, 0.03f, 0.4f,  0.05f, 0.4f,  0.05f,
    0.05f, 0.05f, 0.05f, 0.05f, 0.3f,  0.05f, 0.45f,
    0.1f,  0.15f, 0.2f,  0.02f, 0.35f, 0.03f, 0.15f,
    1.0f/7.0f, 1.0f/7.0f, 1.0f/7.0f, 1.0f/7.0f, 1.0f/7.0f, 1.0f/7.0f, 1.0f/7.0f
};

__device__ float g_partials[NBLOCKS];

__global__ __launch_bounds__(NTHREADS)
void kl_main_kernel(const float* __restrict__ emo,
                    const int* __restrict__ tgt,
                    int B)
{
    __shared__ float s_tn[28];   // normalized target table
    __shared__ float s_c[4];     // sum t*log(t) per class
    __shared__ float s_red[NTHREADS / 32];

    const int tid = threadIdx.x;

    // Build normalized table + per-class entropy constant (threads 0..3)
    if (tid < 4) {
        const float inv = 1.0f / (1.0f + 7.0f * 1e-8f);
        float c = 0.0f;
        #pragma unroll
        for (int j = 0; j < 7; j++) {
            float t = (c_table[tid * 7 + j] + 1e-8f) * inv;
            s_tn[tid * 7 + j] = t;
            c += t * __logf(t);
        }
        s_c[tid] = c;
    }
    __syncthreads();

    float acc = 0.0f;
    const int stride = gridDim.x * blockDim.x;

    for (int row = blockIdx.x * blockDim.x + tid; row < B; row += stride) {
        const float* x = emo + (size_t)row * 7;
        float x0 = x[0], x1 = x[1], x2 = x[2], x3 = x[3];
        float x4 = x[4], x5 = x[5], x6 = x[6];
        int t = tgt[row];
        int idx = ((unsigned)t <= 2u) ? t : 3;

        float m = fmaxf(x0, x1);
        m = fmaxf(m, x2); m = fmaxf(m, x3);
        m = fmaxf(m, x4); m = fmaxf(m, x5); m = fmaxf(m, x6);

        float s = __expf(x0 - m) + __expf(x1 - m) + __expf(x2 - m)
                + __expf(x3 - m) + __expf(x4 - m) + __expf(x5 - m)
                + __expf(x6 - m);

        const float* tn = s_tn + idx * 7;
        float dot = tn[0] * x0;
        dot = fmaf(tn[1], x1, dot);
        dot = fmaf(tn[2], x2, dot);
        dot = fmaf(tn[3], x3, dot);
        dot = fmaf(tn[4], x4, dot);
        dot = fmaf(tn[5], x5, dot);
        dot = fmaf(tn[6], x6, dot);

        // KL_row = C[idx] + m + log(s) - dot   (since sum_j t_j == 1)
        acc += s_c[idx] + m + __logf(s) - dot;
    }

    // warp reduce
    #pragma unroll
    for (int o = 16; o > 0; o >>= 1)
        acc += __shfl_down_sync(0xFFFFFFFFu, acc, o);
    if ((tid & 31) == 0) s_red[tid >> 5] = acc;
    __syncthreads();

    if (tid < (NTHREADS / 32)) {
        acc = s_red[tid];
        #pragma unroll
        for (int o = (NTHREADS / 64); o > 0; o >>= 1)
            acc += __shfl_down_sync(0xFFFFFFFFu, acc, o, NTHREADS / 32);
        if (tid == 0) g_partials[blockIdx.x] = acc;
    }
}

__global__ __launch_bounds__(256)
void kl_final_kernel(float* __restrict__ out, int B)
{
    __shared__ double s[256];
    const int tid = threadIdx.x;
    double acc = 0.0;
    for (int i = tid; i < NBLOCKS; i += 256)
        acc += (double)g_partials[i];
    s[tid] = acc;
    __syncthreads();
    #pragma unroll
    for (int k = 128; k > 0; k >>= 1) {
        if (tid < k) s[tid] += s[tid + k];
        __syncthreads();
    }
    if (tid == 0) out[0] = (float)(s[0] / (double)B);
}

extern "C" void kernel_launch(void* const* d_in, const int* in_sizes, int n_in,
                              void* d_out, int out_size)
{
    // metadata order: fatigue_logits [B,3] (unused), emotion_logits [B,7], fatigue_targets [B] int32
    const float* emo = (const float*)d_in[1];
    const int*   tgt = (const int*)d_in[2];
    const int B = in_sizes[2];

    kl_main_kernel<<<NBLOCKS, NTHREADS>>>(emo, tgt, B);
    kl_final_kernel<<<1, 256>>>((float*)d_out, B);
}

// round 3
// speedup vs baseline: 1.0656x; 1.0656x over previous
#include <cuda_runtime.h>
#include <cuda_bf16.h>

#define NBLOCKS 2048
#define NTHREADS 256

__constant__ float c_table[28] = {
    0.05f, 0.02f, 0.03f, 0.4f,  0.05f, 0.4f,  0.05f,
    0.05f, 0.05f, 0.05f, 0.05f, 0.3f,  0.05f, 0.45f,
    0.1f,  0.15f, 0.2f,  0.02f, 0.35f, 0.03f, 0.15f,
    1.0f/7.0f, 1.0f/7.0f, 1.0f/7.0f, 1.0f/7.0f, 1.0f/7.0f, 1.0f/7.0f, 1.0f/7.0f
};

__device__ double       g_acc   = 0.0;   // reset by last block each launch
__device__ unsigned int g_count = 0;

__global__ __launch_bounds__(NTHREADS)
void kl_fused_kernel(const float* __restrict__ emo,
                     const int*   __restrict__ tgt,
                     float* __restrict__ out,
                     int B)
{
    __shared__ float s_tn[28];
    __shared__ float s_c[4];
    __shared__ float s_red[NTHREADS / 32];

    const int tid = threadIdx.x;

    if (tid < 4) {
        const float inv = 1.0f / (1.0f + 7.0f * 1e-8f);
        float c = 0.0f;
        #pragma unroll
        for (int j = 0; j < 7; j++) {
            float t = (c_table[tid * 7 + j] + 1e-8f) * inv;
            s_tn[tid * 7 + j] = t;
            c += t * __logf(t);
        }
        s_c[tid] = c;
    }
    __syncthreads();

    float acc = 0.0f;

    // ---- vector mainloop: 4 rows / thread (28 floats = 7 aligned float4) ----
    const int ngroups = B >> 2;
    const int gstride = gridDim.x * blockDim.x;
    const float4* emo4 = (const float4*)emo;
    const int4*   tgt4 = (const int4*)tgt;

    for (int g = blockIdx.x * blockDim.x + tid; g < ngroups; g += gstride) {
        float4 v[7];
        #pragma unroll
        for (int i = 0; i < 7; i++) v[i] = emo4[(size_t)g * 7 + i];
        const float* x = (const float*)v;
        int4 t4 = tgt4[g];
        int ti[4] = {t4.x, t4.y, t4.z, t4.w};

        #pragma unroll
        for (int r = 0; r < 4; r++) {
            float x0 = x[r*7+0], x1 = x[r*7+1], x2 = x[r*7+2], x3 = x[r*7+3];
            float x4 = x[r*7+4], x5 = x[r*7+5], x6 = x[r*7+6];
            int idx = ((unsigned)ti[r] <= 2u) ? ti[r] : 3;

            float m = fmaxf(fmaxf(fmaxf(x0, x1), fmaxf(x2, x3)),
                            fmaxf(fmaxf(x4, x5), x6));

            float s = __expf(x0 - m) + __expf(x1 - m) + __expf(x2 - m)
                    + __expf(x3 - m) + __expf(x4 - m) + __expf(x5 - m)
                    + __expf(x6 - m);

            const float* tn = s_tn + idx * 7;
            float dot = tn[0] * x0;
            dot = fmaf(tn[1], x1, dot);
            dot = fmaf(tn[2], x2, dot);
            dot = fmaf(tn[3], x3, dot);
            dot = fmaf(tn[4], x4, dot);
            dot = fmaf(tn[5], x5, dot);
            dot = fmaf(tn[6], x6, dot);

            acc += s_c[idx] + m + __logf(s) - dot;
        }
    }

    // ---- scalar tail (B % 4 rows), done by global thread 0 ----
    if (blockIdx.x == 0 && tid == 0) {
        for (int row = ngroups << 2; row < B; row++) {
            const float* x = emo + (size_t)row * 7;
            float x0 = x[0], x1 = x[1], x2 = x[2], x3 = x[3];
            float x4 = x[4], x5 = x[5], x6 = x[6];
            int t = tgt[row];
            int idx = ((unsigned)t <= 2u) ? t : 3;
            float m = fmaxf(fmaxf(fmaxf(x0, x1), fmaxf(x2, x3)),
                            fmaxf(fmaxf(x4, x5), x6));
            float s = __expf(x0 - m) + __expf(x1 - m) + __expf(x2 - m)
                    + __expf(x3 - m) + __expf(x4 - m) + __expf(x5 - m)
                    + __expf(x6 - m);
            const float* tn = s_tn + idx * 7;
            float dot = tn[0]*x0 + tn[1]*x1 + tn[2]*x2 + tn[3]*x3
                      + tn[4]*x4 + tn[5]*x5 + tn[6]*x6;
            acc += s_c[idx] + m + __logf(s) - dot;
        }
    }

    // ---- block reduction ----
    #pragma unroll
    for (int o = 16; o > 0; o >>= 1)
        acc += __shfl_down_sync(0xFFFFFFFFu, acc, o);
    if ((tid & 31) == 0) s_red[tid >> 5] = acc;
    __syncthreads();

    if (tid < (NTHREADS / 32)) {
        acc = s_red[tid];
        #pragma unroll
        for (int o = (NTHREADS / 64); o > 0; o >>= 1)
            acc += __shfl_down_sync(0xFFFFFFFFu, acc, o, NTHREADS / 32);
    }

    // ---- grid combine: double atomic + last-block-done writes output ----
    if (tid == 0) {
        atomicAdd(&g_acc, (double)acc);
        __threadfence();
        unsigned int done = atomicAdd(&g_count, 1u);
        if (done == gridDim.x - 1) {
            double total = atomicAdd(&g_acc, 0.0);   // atomic coherent read
            out[0] = (float)(total / (double)B);
            // reset for next graph replay
            g_acc   = 0.0;
            g_count = 0u;
        }
    }
}

extern "C" void kernel_launch(void* const* d_in, const int* in_sizes, int n_in,
                              void* d_out, int out_size)
{
    // inputs: fatigue_logits [B,3] (unused), emotion_logits [B,7], fatigue_targets [B] int32
    const float* emo = (const float*)d_in[1];
    const int*   tgt = (const int*)d_in[2];
    const int B = in_sizes[2];

    kl_fused_kernel<<<NBLOCKS, NTHREADS>>>(emo, tgt, (float*)d_out, B);
}